// round 2
// baseline (speedup 1.0000x reference)
#include <cuda_runtime.h>
#include <math.h>

#define B_  32
#define M_  10
#define MN  1010
#define D_  128
#define NODES_TOT (B_*MN*D_)   // 4,136,960

// ------------------------- device scratch -------------------------
__device__ __align__(16) float g_pe_proj[M_*D_];   // (i,k): pe[i] @ W_posproj^T
__device__ __align__(16) float g_vpref[D_];        // Wp @ W_pref
__device__ __align__(16) float g_WnWcT[5*D_];      // (c,d): (Wn @ W_clients)^T
__device__ __align__(16) float g_WnWaT[4*D_];      // (c,d): (Wn @ W_agents)^T
__device__ __align__(16) float g_WcT[5*D_];        // (c,d): W_clients^T
__device__ __align__(16) float g_WaT[4*D_];        // (c,d): W_agents^T
__device__ __align__(16) float g_B1[D_*2];         // (e,c): Wda1 @ W_depot
__device__ __align__(16) float g_B2[D_*4];         // (e,c): Wda2 @ W_agents
__device__ __align__(16) float g_PP[D_*M_];        // (e,i): Wda1 @ pe_proj^T
__device__ __align__(16) float g_Axy[2*D_];        // (c,d): x/y coeff (A1+A2[:, :2]) for pd
__device__ __align__(16) float g_Acs[2*D_];        // (c,d): cap/speed coeff for pd
__device__ __align__(16) float g_P1[M_*D_];        // (i,d)  (alpha folded in)

__device__ __forceinline__ float warp_sum(float v) {
    #pragma unroll
    for (int o = 16; o > 0; o >>= 1) v += __shfl_down_sync(0xffffffffu, v, o);
    return v;
}

// ------------------------- stage A: small fused matrices (multi-block) -------------------------
__global__ void pre1(const float* __restrict__ Wpos, const float* __restrict__ Wfin,
                     const float* __restrict__ Wprf, const float* __restrict__ Wcli,
                     const float* __restrict__ Wag) {
    int blk = blockIdx.x;
    int t = threadIdx.x, w = t >> 5, lane = t & 31;

    if (blk < M_) {
        // pe_proj row i = blk : sum_k pe[i][k] * Wpos[d][k]
        __shared__ float pe[D_];
        if (t < D_) {
            int j = t >> 1;
            float c = -logf(10000.0f) / (float)D_;
            float div = expf((float)(2 * j) * c);
            float ang = (float)blk * div;
            pe[t] = (t & 1) ? cosf(ang) : sinf(ang);
        }
        __syncthreads();
        float p0 = pe[lane*4+0], p1 = pe[lane*4+1], p2 = pe[lane*4+2], p3 = pe[lane*4+3];
        for (int d = w; d < D_; d += 4) {
            float4 wv = *(const float4*)&Wpos[d*D_ + lane*4];
            float s = warp_sum(wv.x*p0 + wv.y*p1 + wv.z*p2 + wv.w*p3);
            if (lane == 0) g_pe_proj[blk*D_ + d] = s;
        }
    } else if (blk == M_) {
        // v_pref[d] = sum_k Wp[d][k] * W_pref[k]
        float4 pv = *(const float4*)&Wprf[lane*4];
        for (int d = w; d < D_; d += 4) {
            float4 wv = *(const float4*)&Wfin[d*384 + 128 + lane*4];
            float s = warp_sum(wv.x*pv.x + wv.y*pv.y + wv.z*pv.z + wv.w*pv.w);
            if (lane == 0) g_vpref[d] = s;
        }
    } else if (blk == M_+1) {
        // WnWcT[c][d] = sum_k Wn[d][k] * Wcli[k][c]
        for (int d = w; d < D_; d += 4) {
            float4 wn = *(const float4*)&Wfin[d*384 + lane*4];
            int k0 = lane * 4;
            float acc[5];
            #pragma unroll
            for (int c = 0; c < 5; c++) {
                acc[c] = wn.x*Wcli[(k0+0)*5+c] + wn.y*Wcli[(k0+1)*5+c]
                       + wn.z*Wcli[(k0+2)*5+c] + wn.w*Wcli[(k0+3)*5+c];
            }
            #pragma unroll
            for (int c = 0; c < 5; c++) {
                float s = warp_sum(acc[c]);
                if (lane == 0) g_WnWcT[c*D_ + d] = s;
            }
        }
    } else if (blk == M_+2) {
        // WnWaT[c][d] = sum_k Wn[d][k] * Wag[k][c]
        for (int d = w; d < D_; d += 4) {
            float4 wn = *(const float4*)&Wfin[d*384 + lane*4];
            int k0 = lane * 4;
            float acc[4];
            #pragma unroll
            for (int c = 0; c < 4; c++) {
                acc[c] = wn.x*Wag[(k0+0)*4+c] + wn.y*Wag[(k0+1)*4+c]
                       + wn.z*Wag[(k0+2)*4+c] + wn.w*Wag[(k0+3)*4+c];
            }
            #pragma unroll
            for (int c = 0; c < 4; c++) {
                float s = warp_sum(acc[c]);
                if (lane == 0) g_WnWaT[c*D_ + d] = s;
            }
        }
    } else {
        // transposes of the tiny weight matrices
        for (int idx = t; idx < 5*D_; idx += blockDim.x) {
            int c = idx / D_, d = idx % D_;
            g_WcT[idx] = Wcli[d*5 + c];
        }
        for (int idx = t; idx < 4*D_; idx += blockDim.x) {
            int c = idx / D_, d = idx % D_;
            g_WaT[idx] = Wag[d*4 + c];
        }
    }
}

// ------------------------- stages B+C fused (single block, 1024 thr) -------------------------
__global__ void __launch_bounds__(1024) pre2(
        const float* __restrict__ Wda, const float* __restrict__ Wdep,
        const float* __restrict__ Wag, const float* __restrict__ Wfin,
        const float* __restrict__ alp) {
    int t = threadIdx.x, w = t >> 5, lane = t & 31;
    int k0 = lane * 4;

    // --- stage B: contract Wda rows with W_depot / W_agents / pe_proj ---
    #pragma unroll
    for (int e = w; e < D_; e += 32) {
        float4 a  = *(const float4*)&Wda[e*256 + k0];         // depot half
        float4 bq = *(const float4*)&Wda[e*256 + 128 + k0];   // agents half

        float acc[16];
        #pragma unroll
        for (int c = 0; c < 2; c++) {
            acc[c] = a.x*Wdep[(k0+0)*2+c] + a.y*Wdep[(k0+1)*2+c]
                   + a.z*Wdep[(k0+2)*2+c] + a.w*Wdep[(k0+3)*2+c];
        }
        #pragma unroll
        for (int c = 0; c < 4; c++) {
            acc[2+c] = bq.x*Wag[(k0+0)*4+c] + bq.y*Wag[(k0+1)*4+c]
                     + bq.z*Wag[(k0+2)*4+c] + bq.w*Wag[(k0+3)*4+c];
        }
        #pragma unroll
        for (int i = 0; i < M_; i++) {
            acc[6+i] = a.x*g_pe_proj[i*D_+k0+0] + a.y*g_pe_proj[i*D_+k0+1]
                     + a.z*g_pe_proj[i*D_+k0+2] + a.w*g_pe_proj[i*D_+k0+3];
        }
        #pragma unroll
        for (int r = 0; r < 16; r++) {
            float s = warp_sum(acc[r]);
            if (lane == 0) {
                if (r < 2)      g_B1[e*2 + r] = s;
                else if (r < 6) g_B2[e*4 + (r-2)] = s;
                else            g_PP[e*M_ + (r-6)] = s;
            }
        }
    }
    __syncthreads();   // global writes by block threads visible after barrier

    // --- stage C: contract with Wd ---
    float alpha = alp[0];
    int e0 = lane * 4;
    #pragma unroll
    for (int d = w; d < D_; d += 32) {
        float4 wd = *(const float4*)&Wfin[d*384 + 256 + e0];  // Wd[d][e0..e0+3]

        float acc[16];
        // Axy: x/y coeff combining A1 and A2 first two columns
        #pragma unroll
        for (int c = 0; c < 2; c++) {
            acc[c] = wd.x*(g_B1[(e0+0)*2+c] + g_B2[(e0+0)*4+c])
                   + wd.y*(g_B1[(e0+1)*2+c] + g_B2[(e0+1)*4+c])
                   + wd.z*(g_B1[(e0+2)*2+c] + g_B2[(e0+2)*4+c])
                   + wd.w*(g_B1[(e0+3)*2+c] + g_B2[(e0+3)*4+c]);
        }
        // Acs: cap/speed coeff (A2 cols 2,3)
        #pragma unroll
        for (int c = 2; c < 4; c++) {
            acc[c] = wd.x*g_B2[(e0+0)*4+c] + wd.y*g_B2[(e0+1)*4+c]
                   + wd.z*g_B2[(e0+2)*4+c] + wd.w*g_B2[(e0+3)*4+c];
        }
        #pragma unroll
        for (int i = 0; i < M_; i++) {
            acc[6+i] = wd.x*g_PP[(e0+0)*M_+i] + wd.y*g_PP[(e0+1)*M_+i]
                     + wd.z*g_PP[(e0+2)*M_+i] + wd.w*g_PP[(e0+3)*M_+i];
        }
        #pragma unroll
        for (int r = 0; r < 16; r++) {
            float s = warp_sum(acc[r]);
            if (lane == 0) {
                if (r < 2)      g_Axy[r*D_ + d] = s;
                else if (r < 4) g_Acs[(r-2)*D_ + d] = s;
                else if (r >= 6) g_P1[(r-6)*D_ + d] = alpha * s;
            }
        }
    }
}

// ------------------------- main kernel: nodes + combined (store-bound) -------------------------
__global__ void __launch_bounds__(128) mk(
        const float* __restrict__ locs, const float* __restrict__ cap,
        const float* __restrict__ spd,  const float* __restrict__ dem,
        const float* __restrict__ pref, float* __restrict__ out) {
    int b = blockIdx.y;
    int w = threadIdx.x >> 5, lane = threadIdx.x & 31;
    int j = blockIdx.x * 4 + w;

    // agent features for this batch -> shared (broadcast to all warps)
    __shared__ float sx[M_], sy[M_], sc[M_], ss[M_];
    if (threadIdx.x < M_) {
        int i = threadIdx.x;
        sx[i] = locs[(b*MN+i)*2+0];
        sy[i] = locs[(b*MN+i)*2+1];
        sc[i] = cap[b*M_+i] * 0.025f;
        ss[i] = spd[b*M_+i];
    }
    __syncthreads();
    if (j >= MN) return;
    int d0 = lane * 4;

    float4 vp = *(const float4*)&g_vpref[d0];
    float4 ax = *(const float4*)&g_Axy[0*D_+d0];
    float4 ay = *(const float4*)&g_Axy[1*D_+d0];
    float4 ac = *(const float4*)&g_Acs[0*D_+d0];
    float4 as_= *(const float4*)&g_Acs[1*D_+d0];

    float4 ce, pn;
    float x = locs[(b*MN+j)*2+0], y = locs[(b*MN+j)*2+1];

    if (j < M_) {
        float f2 = sc[j];
        float f3 = ss[j];
        float4 w0 = *(const float4*)&g_WaT[0*D_+d0];
        float4 w1 = *(const float4*)&g_WaT[1*D_+d0];
        float4 w2 = *(const float4*)&g_WaT[2*D_+d0];
        float4 w3 = *(const float4*)&g_WaT[3*D_+d0];
        ce.x = x*w0.x + y*w1.x + f2*w2.x + f3*w3.x;
        ce.y = x*w0.y + y*w1.y + f2*w2.y + f3*w3.y;
        ce.z = x*w0.z + y*w1.z + f2*w2.z + f3*w3.z;
        ce.w = x*w0.w + y*w1.w + f2*w2.w + f3*w3.w;
        float4 n0 = *(const float4*)&g_WnWaT[0*D_+d0];
        float4 n1 = *(const float4*)&g_WnWaT[1*D_+d0];
        float4 n2 = *(const float4*)&g_WnWaT[2*D_+d0];
        float4 n3 = *(const float4*)&g_WnWaT[3*D_+d0];
        pn.x = x*n0.x + y*n1.x + f2*n2.x + f3*n3.x;
        pn.y = x*n0.y + y*n1.y + f2*n2.y + f3*n3.y;
        pn.z = x*n0.z + y*n1.z + f2*n2.z + f3*n3.z;
        pn.w = x*n0.w + y*n1.w + f2*n2.w + f3*n3.w;
    } else {
        float dx = x - sx[0];
        float dy = y - sy[0];
        float dist = sqrtf(dx*dx + dy*dy);
        float ang  = atan2f(dy, dx);
        float f2   = dem[b*MN+j] * 0.025f;
        float4 w0 = *(const float4*)&g_WcT[0*D_+d0];
        float4 w1 = *(const float4*)&g_WcT[1*D_+d0];
        float4 w2 = *(const float4*)&g_WcT[2*D_+d0];
        float4 w3 = *(const float4*)&g_WcT[3*D_+d0];
        float4 w4 = *(const float4*)&g_WcT[4*D_+d0];
        ce.x = x*w0.x + y*w1.x + f2*w2.x + dist*w3.x + ang*w4.x;
        ce.y = x*w0.y + y*w1.y + f2*w2.y + dist*w3.y + ang*w4.y;
        ce.z = x*w0.z + y*w1.z + f2*w2.z + dist*w3.z + ang*w4.z;
        ce.w = x*w0.w + y*w1.w + f2*w2.w + dist*w3.w + ang*w4.w;
        float4 n0 = *(const float4*)&g_WnWcT[0*D_+d0];
        float4 n1 = *(const float4*)&g_WnWcT[1*D_+d0];
        float4 n2 = *(const float4*)&g_WnWcT[2*D_+d0];
        float4 n3 = *(const float4*)&g_WnWcT[3*D_+d0];
        float4 n4 = *(const float4*)&g_WnWcT[4*D_+d0];
        pn.x = x*n0.x + y*n1.x + f2*n2.x + dist*n3.x + ang*n4.x;
        pn.y = x*n0.y + y*n1.y + f2*n2.y + dist*n3.y + ang*n4.y;
        pn.z = x*n0.z + y*n1.z + f2*n2.z + dist*n3.z + ang*n4.z;
        pn.w = x*n0.w + y*n1.w + f2*n2.w + dist*n3.w + ang*n4.w;
    }

    // output 1: nodes_embedding (streaming store)
    __stcs((float4*)&out[((size_t)b*MN + j)*D_ + d0], ce);

    // output 2: combined_embedding with inline depot-agents projection
    const float* pp = pref + (size_t)(b*M_)*MN + j;
    float* oc = out + NODES_TOT + ((size_t)(b*M_)*MN + (size_t)j)*D_ + d0;
    #pragma unroll
    for (int i = 0; i < M_; i++) {
        float p  = pp[(size_t)i*MN];
        float xi = sx[i], yi = sy[i], ci = sc[i], si = ss[i];
        float4 p1 = *(const float4*)&g_P1[i*D_ + d0];
        float4 o;
        o.x = pn.x + p*vp.x + (ax.x*xi + ay.x*yi + ac.x*ci + as_.x*si + p1.x);
        o.y = pn.y + p*vp.y + (ax.y*xi + ay.y*yi + ac.y*ci + as_.y*si + p1.y);
        o.z = pn.z + p*vp.z + (ax.z*xi + ay.z*yi + ac.z*ci + as_.z*si + p1.z);
        o.w = pn.w + p*vp.w + (ax.w*xi + ay.w*yi + ac.w*ci + as_.w*si + p1.w);
        __stcs((float4*)&oc[(size_t)i*MN*D_], o);
    }
}

// ------------------------- launch -------------------------
extern "C" void kernel_launch(void* const* d_in, const int* in_sizes, int n_in,
                              void* d_out, int out_size) {
    const float* locs = (const float*)d_in[0];
    const float* cap  = (const float*)d_in[1];
    const float* spd  = (const float*)d_in[2];
    const float* dem  = (const float*)d_in[3];
    const float* pref = (const float*)d_in[4];
    // d_in[5] = action_mask (unused)
    const float* Wdep = (const float*)d_in[6];
    const float* Wpos = (const float*)d_in[7];
    const float* alp  = (const float*)d_in[8];
    const float* Wag  = (const float*)d_in[9];
    const float* Wda  = (const float*)d_in[10];
    const float* Wcli = (const float*)d_in[11];
    const float* Wprf = (const float*)d_in[12];
    const float* Wfin = (const float*)d_in[13];
    float* out = (float*)d_out;

    pre1<<<M_ + 4, 128>>>(Wpos, Wfin, Wprf, Wcli, Wag);
    pre2<<<1, 1024>>>(Wda, Wdep, Wag, Wfin, alp);
    mk<<<dim3((MN + 3) / 4, B_), 128>>>(locs, cap, spd, dem, pref, out);
}

// round 4
// speedup vs baseline: 1.1688x; 1.1688x over previous
#include <cuda_runtime.h>
#include <math.h>

#define B_  32
#define M_  10
#define MN  1010
#define D_  128
#define NODES_TOT (B_*MN*D_)   // 4,136,960

// ------------------------- device scratch -------------------------
__device__ __align__(16) float g_pe_proj[M_*D_];   // (i,d): pe[i] @ W_posproj^T
__device__ __align__(16) float g_vpref[D_];        // Wp @ W_pref
__device__ __align__(16) float g_WnWcT[5*D_];      // (c,d): (Wn @ W_clients)^T
__device__ __align__(16) float g_WnWaT[4*D_];      // (c,d): (Wn @ W_agents)^T
__device__ __align__(16) float g_WcT[5*D_];        // (c,d): W_clients^T
__device__ __align__(16) float g_WaT[4*D_];        // (c,d): W_agents^T
__device__ __align__(16) float g_B1[D_*2];         // (e,c): Wda1 @ W_depot
__device__ __align__(16) float g_B2[D_*4];         // (e,c): Wda2 @ W_agents
__device__ __align__(16) float g_Axy[2*D_];        // (c,d): x/y coeff for pd
__device__ __align__(16) float g_Acs[2*D_];        // (c,d): cap/speed coeff for pd
__device__ __align__(16) float g_P1[M_*D_];        // (i,d)  (alpha folded in)

// ------------------------- K1: independent stages, one output per thread -------------------------
__global__ void __launch_bounds__(128) k1(
        const float* __restrict__ Wpos, const float* __restrict__ Wfin,
        const float* __restrict__ Wprf, const float* __restrict__ Wcli,
        const float* __restrict__ Wag,  const float* __restrict__ Wdep,
        const float* __restrict__ Wda) {
    int blk = blockIdx.x, t = threadIdx.x;
    __shared__ float sm[1280];

    if (blk < M_) {
        // pe_proj[i=blk][d=t] = sum_k pe[k] * Wpos[d][k]
        {
            int j = t >> 1;
            float c = -logf(10000.0f) / (float)D_;
            float div = expf((float)(2 * j) * c);
            float ang = (float)blk * div;
            sm[t] = (t & 1) ? cosf(ang) : sinf(ang);
        }
        __syncthreads();
        float acc = 0.f;
        #pragma unroll
        for (int kk = 0; kk < 32; kk++) {
            float4 wv = *(const float4*)&Wpos[t*D_ + kk*4];
            acc += wv.x*sm[4*kk] + wv.y*sm[4*kk+1] + wv.z*sm[4*kk+2] + wv.w*sm[4*kk+3];
        }
        g_pe_proj[blk*D_ + t] = acc;
    } else if (blk == M_) {
        // vpref[d=t] = sum_k Wp[d][k] * W_pref[k]
        sm[t] = Wprf[t];
        __syncthreads();
        float acc = 0.f;
        #pragma unroll
        for (int kk = 0; kk < 32; kk++) {
            float4 wv = *(const float4*)&Wfin[t*384 + 128 + kk*4];
            acc += wv.x*sm[4*kk] + wv.y*sm[4*kk+1] + wv.z*sm[4*kk+2] + wv.w*sm[4*kk+3];
        }
        g_vpref[t] = acc;
    } else if (blk == M_+1) {
        // WnWcT / WnWaT (+ transposes WcT/WaT)
        for (int idx = t; idx < 5*D_; idx += 128) sm[idx] = Wcli[idx];
        for (int idx = t; idx < 4*D_; idx += 128) sm[640 + idx] = Wag[idx];
        __syncthreads();
        float an[5] = {0,0,0,0,0};
        float aa[4] = {0,0,0,0};
        #pragma unroll
        for (int kk = 0; kk < 32; kk++) {
            float4 wn = *(const float4*)&Wfin[t*384 + kk*4];
            int k0 = kk*4;
            #pragma unroll
            for (int c = 0; c < 5; c++) {
                an[c] += wn.x*sm[(k0+0)*5+c] + wn.y*sm[(k0+1)*5+c]
                       + wn.z*sm[(k0+2)*5+c] + wn.w*sm[(k0+3)*5+c];
            }
            #pragma unroll
            for (int c = 0; c < 4; c++) {
                aa[c] += wn.x*sm[640+(k0+0)*4+c] + wn.y*sm[640+(k0+1)*4+c]
                       + wn.z*sm[640+(k0+2)*4+c] + wn.w*sm[640+(k0+3)*4+c];
            }
        }
        #pragma unroll
        for (int c = 0; c < 5; c++) { g_WnWcT[c*D_ + t] = an[c]; g_WcT[c*D_ + t] = sm[t*5 + c]; }
        #pragma unroll
        for (int c = 0; c < 4; c++) { g_WnWaT[c*D_ + t] = aa[c]; g_WaT[c*D_ + t] = sm[640 + t*4 + c]; }
    } else {
        // B1[e][c] = Wda1[e] . Wdep[:,c] ;  B2[e][c] = Wda2[e] . Wag[:,c]
        for (int idx = t; idx < 2*D_; idx += 128) sm[idx] = Wdep[idx];
        for (int idx = t; idx < 4*D_; idx += 128) sm[256 + idx] = Wag[idx];
        __syncthreads();
        float b1[2] = {0,0};
        float b2[4] = {0,0,0,0};
        #pragma unroll
        for (int kk = 0; kk < 32; kk++) {
            int k0 = kk*4;
            float4 a = *(const float4*)&Wda[t*256 + k0];
            #pragma unroll
            for (int c = 0; c < 2; c++) {
                b1[c] += a.x*sm[(k0+0)*2+c] + a.y*sm[(k0+1)*2+c]
                       + a.z*sm[(k0+2)*2+c] + a.w*sm[(k0+3)*2+c];
            }
            float4 q = *(const float4*)&Wda[t*256 + 128 + k0];
            #pragma unroll
            for (int c = 0; c < 4; c++) {
                b2[c] += q.x*sm[256+(k0+0)*4+c] + q.y*sm[256+(k0+1)*4+c]
                       + q.z*sm[256+(k0+2)*4+c] + q.w*sm[256+(k0+3)*4+c];
            }
        }
        #pragma unroll
        for (int c = 0; c < 2; c++) g_B1[t*2 + c] = b1[c];
        #pragma unroll
        for (int c = 0; c < 4; c++) g_B2[t*4 + c] = b2[c];
    }
}

// ------------------------- K2: chained stages (needs pe_proj, B1, B2) -------------------------
__global__ void __launch_bounds__(128) k2(
        const float* __restrict__ Wda, const float* __restrict__ Wfin,
        const float* __restrict__ alp) {
    int blk = blockIdx.x, t = threadIdx.x;
    __shared__ float sA[D_];
    __shared__ float sB[768];

    if (blk < M_) {
        // PP[e] = Wda1[e] . pe_proj[i]   then   P1[i][d] = alpha * Wd[d] . PP
        sA[t] = g_pe_proj[blk*D_ + t];
        __syncthreads();
        float acc = 0.f;
        #pragma unroll
        for (int kk = 0; kk < 32; kk++) {
            float4 a = *(const float4*)&Wda[t*256 + kk*4];
            acc += a.x*sA[4*kk] + a.y*sA[4*kk+1] + a.z*sA[4*kk+2] + a.w*sA[4*kk+3];
        }
        sB[t] = acc;   // PP[e=t]
        __syncthreads();
        float acc2 = 0.f;
        #pragma unroll
        for (int kk = 0; kk < 32; kk++) {
            float4 wd = *(const float4*)&Wfin[t*384 + 256 + kk*4];
            acc2 += wd.x*sB[4*kk] + wd.y*sB[4*kk+1] + wd.z*sB[4*kk+2] + wd.w*sB[4*kk+3];
        }
        g_P1[blk*D_ + t] = alp[0] * acc2;
    } else {
        // Axy[c][d], Acs[c][d] from B1/B2 contracted with Wd rows
        for (int idx = t; idx < 2*D_; idx += 128) sB[idx] = g_B1[idx];
        for (int idx = t; idx < 4*D_; idx += 128) sB[256 + idx] = g_B2[idx];
        __syncthreads();
        float axy[2] = {0,0};
        float acs[2] = {0,0};
        #pragma unroll
        for (int kk = 0; kk < 32; kk++) {
            int e0 = kk*4;
            float4 wd = *(const float4*)&Wfin[t*384 + 256 + e0];
            #pragma unroll
            for (int c = 0; c < 2; c++) {
                axy[c] += wd.x*(sB[(e0+0)*2+c] + sB[256+(e0+0)*4+c])
                        + wd.y*(sB[(e0+1)*2+c] + sB[256+(e0+1)*4+c])
                        + wd.z*(sB[(e0+2)*2+c] + sB[256+(e0+2)*4+c])
                        + wd.w*(sB[(e0+3)*2+c] + sB[256+(e0+3)*4+c]);
                acs[c] += wd.x*sB[256+(e0+0)*4+c+2] + wd.y*sB[256+(e0+1)*4+c+2]
                        + wd.z*sB[256+(e0+2)*4+c+2] + wd.w*sB[256+(e0+3)*4+c+2];
            }
        }
        #pragma unroll
        for (int c = 0; c < 2; c++) { g_Axy[c*D_ + t] = axy[c]; g_Acs[c*D_ + t] = acs[c]; }
    }
}

// ------------------------- main kernel: nodes + combined (store-bound) -------------------------
__global__ void __launch_bounds__(128) mk(
        const float* __restrict__ locs, const float* __restrict__ cap,
        const float* __restrict__ spd,  const float* __restrict__ dem,
        const float* __restrict__ pref, float* __restrict__ out) {
    int b = blockIdx.y;
    int w = threadIdx.x >> 5, lane = threadIdx.x & 31;
    int j = blockIdx.x * 4 + w;

    __shared__ float sx[M_], sy[M_], sc[M_], ss[M_];
    if (threadIdx.x < M_) {
        int i = threadIdx.x;
        sx[i] = locs[(b*MN+i)*2+0];
        sy[i] = locs[(b*MN+i)*2+1];
        sc[i] = cap[b*M_+i] * 0.025f;
        ss[i] = spd[b*M_+i];
    }
    __syncthreads();
    if (j >= MN) return;
    int d0 = lane * 4;

    float4 vp = *(const float4*)&g_vpref[d0];
    float4 ax = *(const float4*)&g_Axy[0*D_+d0];
    float4 ay = *(const float4*)&g_Axy[1*D_+d0];
    float4 ac = *(const float4*)&g_Acs[0*D_+d0];
    float4 as_= *(const float4*)&g_Acs[1*D_+d0];

    float4 ce, pn;
    float x = locs[(b*MN+j)*2+0], y = locs[(b*MN+j)*2+1];

    if (j < M_) {
        float f2 = sc[j];
        float f3 = ss[j];
        float4 w0 = *(const float4*)&g_WaT[0*D_+d0];
        float4 w1 = *(const float4*)&g_WaT[1*D_+d0];
        float4 w2 = *(const float4*)&g_WaT[2*D_+d0];
        float4 w3 = *(const float4*)&g_WaT[3*D_+d0];
        ce.x = x*w0.x + y*w1.x + f2*w2.x + f3*w3.x;
        ce.y = x*w0.y + y*w1.y + f2*w2.y + f3*w3.y;
        ce.z = x*w0.z + y*w1.z + f2*w2.z + f3*w3.z;
        ce.w = x*w0.w + y*w1.w + f2*w2.w + f3*w3.w;
        float4 n0 = *(const float4*)&g_WnWaT[0*D_+d0];
        float4 n1 = *(const float4*)&g_WnWaT[1*D_+d0];
        float4 n2 = *(const float4*)&g_WnWaT[2*D_+d0];
        float4 n3 = *(const float4*)&g_WnWaT[3*D_+d0];
        pn.x = x*n0.x + y*n1.x + f2*n2.x + f3*n3.x;
        pn.y = x*n0.y + y*n1.y + f2*n2.y + f3*n3.y;
        pn.z = x*n0.z + y*n1.z + f2*n2.z + f3*n3.z;
        pn.w = x*n0.w + y*n1.w + f2*n2.w + f3*n3.w;
    } else {
        float dx = x - sx[0];
        float dy = y - sy[0];
        float dist = sqrtf(dx*dx + dy*dy);
        float ang  = atan2f(dy, dx);
        float f2   = dem[b*MN+j] * 0.025f;
        float4 w0 = *(const float4*)&g_WcT[0*D_+d0];
        float4 w1 = *(const float4*)&g_WcT[1*D_+d0];
        float4 w2 = *(const float4*)&g_WcT[2*D_+d0];
        float4 w3 = *(const float4*)&g_WcT[3*D_+d0];
        float4 w4 = *(const float4*)&g_WcT[4*D_+d0];
        ce.x = x*w0.x + y*w1.x + f2*w2.x + dist*w3.x + ang*w4.x;
        ce.y = x*w0.y + y*w1.y + f2*w2.y + dist*w3.y + ang*w4.y;
        ce.z = x*w0.z + y*w1.z + f2*w2.z + dist*w3.z + ang*w4.z;
        ce.w = x*w0.w + y*w1.w + f2*w2.w + dist*w3.w + ang*w4.w;
        float4 n0 = *(const float4*)&g_WnWcT[0*D_+d0];
        float4 n1 = *(const float4*)&g_WnWcT[1*D_+d0];
        float4 n2 = *(const float4*)&g_WnWcT[2*D_+d0];
        float4 n3 = *(const float4*)&g_WnWcT[3*D_+d0];
        float4 n4 = *(const float4*)&g_WnWcT[4*D_+d0];
        pn.x = x*n0.x + y*n1.x + f2*n2.x + dist*n3.x + ang*n4.x;
        pn.y = x*n0.y + y*n1.y + f2*n2.y + dist*n3.y + ang*n4.y;
        pn.z = x*n0.z + y*n1.z + f2*n2.z + dist*n3.z + ang*n4.z;
        pn.w = x*n0.w + y*n1.w + f2*n2.w + dist*n3.w + ang*n4.w;
    }

    // output 1: nodes_embedding
    *(float4*)&out[((size_t)b*MN + j)*D_ + d0] = ce;

    // output 2: combined_embedding with inline depot-agents projection
    const float* pp = pref + (size_t)(b*M_)*MN + j;
    float* oc = out + NODES_TOT + ((size_t)(b*M_)*MN + (size_t)j)*D_ + d0;
    #pragma unroll
    for (int i = 0; i < M_; i++) {
        float p  = pp[(size_t)i*MN];
        float xi = sx[i], yi = sy[i], ci = sc[i], si = ss[i];
        float4 p1 = *(const float4*)&g_P1[i*D_ + d0];
        float4 o;
        o.x = pn.x + p*vp.x + (ax.x*xi + ay.x*yi + ac.x*ci + as_.x*si + p1.x);
        o.y = pn.y + p*vp.y + (ax.y*xi + ay.y*yi + ac.y*ci + as_.y*si + p1.y);
        o.z = pn.z + p*vp.z + (ax.z*xi + ay.z*yi + ac.z*ci + as_.z*si + p1.z);
        o.w = pn.w + p*vp.w + (ax.w*xi + ay.w*yi + ac.w*ci + as_.w*si + p1.w);
        *(float4*)&oc[(size_t)i*MN*D_] = o;
    }
}

// ------------------------- launch -------------------------
extern "C" void kernel_launch(void* const* d_in, const int* in_sizes, int n_in,
                              void* d_out, int out_size) {
    const float* locs = (const float*)d_in[0];
    const float* cap  = (const float*)d_in[1];
    const float* spd  = (const float*)d_in[2];
    const float* dem  = (const float*)d_in[3];
    const float* pref = (const float*)d_in[4];
    // d_in[5] = action_mask (unused)
    const float* Wdep = (const float*)d_in[6];
    const float* Wpos = (const float*)d_in[7];
    const float* alp  = (const float*)d_in[8];
    const float* Wag  = (const float*)d_in[9];
    const float* Wda  = (const float*)d_in[10];
    const float* Wcli = (const float*)d_in[11];
    const float* Wprf = (const float*)d_in[12];
    const float* Wfin = (const float*)d_in[13];
    float* out = (float*)d_out;

    k1<<<M_ + 3, 128>>>(Wpos, Wfin, Wprf, Wcli, Wag, Wdep, Wda);
    k2<<<M_ + 1, 128>>>(Wda, Wfin, alp);
    mk<<<dim3((MN + 3) / 4, B_), 128>>>(locs, cap, spd, dem, pref, out);
}